// round 9
// baseline (speedup 1.0000x reference)
#include <cuda_runtime.h>
#include <cuda_fp16.h>
#include <math.h>

#define NN 100000
#define NE 1200000
#define FIN 128
#define FHID 64
#define FOUT 40

typedef unsigned long long ull;

// ---------------- scratch (device globals) ----------------
// g_zero: [0,NN) = degree histogram, [NN, NN+128) = scan ready-flags. One memset.
__device__ int    g_zero[NN + 128];
__device__ int    g_rowptr[NN + 1];
__device__ int    g_rank[NE];               // per-edge rank within its dst segment
__device__ int    g_col[NE];
__device__ float  g_dis[NN];
__device__ __half g_Hh[(size_t)NN * FHID];  // fp16 message buffer (layers 1-2)
__device__ float  g_H[(size_t)NN * FHID];   // fp32 message buffer (layer 3)
__device__ float  g_Z[(size_t)NN * FHID];   // aggregated fp32 buffer

constexpr int SCAN_B = 1024;
constexpr int NBLK   = (NN + SCAN_B - 1) / SCAN_B;  // 98

// ---------------- side stream for capture fork-join (created pre-main) ----------------
struct SideStream {
    cudaStream_t s1;
    cudaEvent_t evFork, evJoin;
    SideStream() {
        cudaStreamCreateWithFlags(&s1, cudaStreamNonBlocking);
        cudaEventCreateWithFlags(&evFork, cudaEventDisableTiming);
        cudaEventCreateWithFlags(&evJoin, cudaEventDisableTiming);
    }
};
static SideStream g_ss;

// ---------------- packed f32x2 helpers (Blackwell FFMA2) ----------------
__device__ __forceinline__ ull bcast2(float f) {
    ull r;
    asm("mov.b64 %0, {%1, %1};" : "=l"(r) : "f"(f));
    return r;
}
__device__ __forceinline__ void fma2(ull& d, ull a, ull b) {
    asm("fma.rn.f32x2 %0, %1, %2, %0;" : "+l"(d) : "l"(a), "l"(b));
}
__device__ __forceinline__ void unpack2(float& lo, float& hi, ull v) {
    asm("mov.b64 {%0, %1}, %2;" : "=f"(lo), "=f"(hi) : "l"(v));
}

// ---------------- per-block edge dtype detection ----------------
__device__ __forceinline__ int detect_is64(const int* e) {
    int t = threadIdx.x;
    int pred = 1;
    if (t < 128) pred = (e[2 * t + 1] == 0);
    return __syncthreads_and(pred);
}

__device__ __forceinline__ int edge_at(const void* e, long long idx, int is64) {
    if (is64) return (int)((const long long*)e)[idx];
    return ((const int*)e)[idx];
}

// ---------------- degree histogram; atomic return value = per-edge rank ----------------
__global__ void k_hist(const void* __restrict__ e) {
    int is64 = detect_is64((const int*)e);
    int i = blockIdx.x * blockDim.x + threadIdx.x;
    if (i < NE) {
        int d = edge_at(e, (long long)NE + i, is64);
        g_rank[i] = atomicAdd(&g_zero[d], 1);
    }
}

// ---------------- single-pass scan: deg -> rowptr, dis ----------------
__global__ void __launch_bounds__(SCAN_B) k_scan_fused() {
    __shared__ int wsum[32];
    __shared__ int s_off;
    int b    = blockIdx.x;
    int tid  = threadIdx.x;
    int lane = tid & 31;
    int wid  = tid >> 5;
    int idx  = b * SCAN_B + tid;
    int* ready = &g_zero[NN];

    int v = (idx < NN) ? g_zero[idx] : 0;
    if (idx < NN) g_dis[idx] = rsqrtf((float)(v + 1));
    if (tid == 0) s_off = 0;

    int x = v;
#pragma unroll
    for (int off = 1; off < 32; off <<= 1) {
        int y = __shfl_up_sync(0xFFFFFFFFu, x, off);
        if (lane >= off) x += y;
    }
    if (lane == 31) wsum[wid] = x;
    __syncthreads();
    if (wid == 0) {
        int w = wsum[lane];
#pragma unroll
        for (int off = 1; off < 32; off <<= 1) {
            int y = __shfl_up_sync(0xFFFFFFFFu, w, off);
            if (lane >= off) w += y;
        }
        wsum[lane] = w;
    }
    __syncthreads();
    int inc = x + ((wid > 0) ? wsum[wid - 1] : 0);

    if (tid == SCAN_B - 1)
        atomicExch(&ready[b], inc + 1);

    if (tid < b) {
        int a;
        do { a = atomicAdd(&ready[tid], 0); } while (a == 0);
        atomicAdd(&s_off, a - 1);
    }
    __syncthreads();
    int off = s_off;

    if (idx < NN)
        g_rowptr[idx + 1] = off + inc;
    if (idx == 0) g_rowptr[0] = 0;
}

// ---------------- CSR fill: atomic-free (pos = rowptr[d] + rank[i]) ----------------
__global__ void k_fill(const void* __restrict__ e) {
    int is64 = detect_is64((const int*)e);
    int i = blockIdx.x * blockDim.x + threadIdx.x;
    if (i < NE) {
        int d = edge_at(e, (long long)NE + i, is64);
        int s = edge_at(e, i, is64);
        int r = g_rank[i];
        g_col[g_rowptr[d] + r] = s;
    }
}

// ---------------- GEMM (64x64 tile, known good) ----------------
// out[i,c] = (SCALE ? dis[i] : 1) * sum_k X[i,k]*W[k,c]; OUTH requires NOUT==64.
template <int K, int NOUT, bool SCALE, bool OUTH>
__global__ void __launch_bounds__(128) k_gemm(const float* __restrict__ X,
                                              const float* __restrict__ W,
                                              void* __restrict__ outv) {
    constexpr int BM = 64;
    constexpr int BN = 64;
    constexpr int KC = 32;
    __shared__ float Ws[K][BN];
    __shared__ float Xs[KC][BM + 4];

    int t  = threadIdx.x;
    int m0 = blockIdx.x * BM;
    int rbase = (t >> 4) * 8;
    int cbase = (t & 15) * 4;

    for (int i = t; i < K * BN; i += 128) {
        int k = i / BN, c = i % BN;
        Ws[k][c] = (c < NOUT) ? W[k * NOUT + c] : 0.0f;
    }

    ull acc[4][4];
#pragma unroll
    for (int rp = 0; rp < 4; rp++)
#pragma unroll
        for (int c = 0; c < 4; c++) acc[rp][c] = 0ull;

    __syncthreads();

    for (int kc = 0; kc < K; kc += KC) {
#pragma unroll
        for (int i = 0; i < 4; i++) {
            int v = t + i * 128;
            int r = v >> 3;
            int q = v & 7;
            int row = m0 + r;
            float4 f = make_float4(0.f, 0.f, 0.f, 0.f);
            if (row < NN)
                f = *(const float4*)&X[(size_t)row * K + kc + q * 4];
            Xs[q * 4 + 0][r] = f.x;
            Xs[q * 4 + 1][r] = f.y;
            Xs[q * 4 + 2][r] = f.z;
            Xs[q * 4 + 3][r] = f.w;
        }
        __syncthreads();

#pragma unroll
        for (int kk = 0; kk < KC; kk++) {
            float4 wv = *(const float4*)&Ws[kc + kk][cbase];
            ull wb0 = bcast2(wv.x);
            ull wb1 = bcast2(wv.y);
            ull wb2 = bcast2(wv.z);
            ull wb3 = bcast2(wv.w);
            ulonglong2 xp0 = *(const ulonglong2*)&Xs[kk][rbase];
            ulonglong2 xp1 = *(const ulonglong2*)&Xs[kk][rbase + 4];
            ull xr[4] = {xp0.x, xp0.y, xp1.x, xp1.y};
#pragma unroll
            for (int rp = 0; rp < 4; rp++) {
                fma2(acc[rp][0], xr[rp], wb0);
                fma2(acc[rp][1], xr[rp], wb1);
                fma2(acc[rp][2], xr[rp], wb2);
                fma2(acc[rp][3], xr[rp], wb3);
            }
        }
        __syncthreads();
    }

#pragma unroll
    for (int rp = 0; rp < 4; rp++) {
        int row0 = m0 + rbase + 2 * rp;
        int row1 = row0 + 1;
        float ds0 = 1.f, ds1 = 1.f;
        if (SCALE) {
            ds0 = (row0 < NN) ? g_dis[row0] : 0.f;
            ds1 = (row1 < NN) ? g_dis[row1] : 0.f;
        }
        float v0[4], v1[4];
#pragma unroll
        for (int c = 0; c < 4; c++) unpack2(v0[c], v1[c], acc[rp][c]);

        if (OUTH) {
            __half* out = (__half*)outv;
            if (row0 < NN) {
                __half2 h0 = __floats2half2_rn(v0[0] * ds0, v0[1] * ds0);
                __half2 h1 = __floats2half2_rn(v0[2] * ds0, v0[3] * ds0);
                uint2 u; u.x = *(unsigned*)&h0; u.y = *(unsigned*)&h1;
                *(uint2*)&out[(size_t)row0 * 64 + cbase] = u;
            }
            if (row1 < NN) {
                __half2 h0 = __floats2half2_rn(v1[0] * ds1, v1[1] * ds1);
                __half2 h1 = __floats2half2_rn(v1[2] * ds1, v1[3] * ds1);
                uint2 u; u.x = *(unsigned*)&h0; u.y = *(unsigned*)&h1;
                *(uint2*)&out[(size_t)row1 * 64 + cbase] = u;
            }
        } else {
            float* out = (float*)outv;
#pragma unroll
            for (int c = 0; c < 4; c++) {
                int cc = cbase + c;
                if (cc < NOUT) {
                    if (row0 < NN) out[(size_t)row0 * NOUT + cc] = v0[c] * ds0;
                    if (row1 < NN) out[(size_t)row1 * NOUT + cc] = v1[c] * ds1;
                }
            }
        }
    }
}

// ---------------- fp16 aggregation (F=64): warp per node, fp32 accumulate ----------------
// SRCSCALE=false: H pre-scaled by dis; out = relu(dis[d]*(Σ H[s] + H[d]) + b)
// SRCSCALE=true : H unscaled;         out = relu(dis[d]*(Σ dis[s]H[s] + dis[d]H[d]) + b)
template <bool SRCSCALE>
__global__ void __launch_bounds__(256) k_agg_h(const __half2* __restrict__ H,
                                               const float* __restrict__ bias,
                                               float* __restrict__ out) {
    constexpr int L = FHID / 2;  // 32 half2 per row = full warp
    int warp = (blockIdx.x * blockDim.x + threadIdx.x) >> 5;
    int lane = threadIdx.x & 31;
    if (warp >= NN) return;

    int s = g_rowptr[warp];
    int e = g_rowptr[warp + 1];
    float dn = g_dis[warp];

    float2 self = __half22float2(H[(size_t)warp * L + lane]);
    float sc = SRCSCALE ? dn : 1.f;
    float ax = self.x * sc, ay = self.y * sc;

    int j = s;
    for (; j + 4 <= e; j += 4) {
        int i0 = g_col[j], i1 = g_col[j + 1], i2 = g_col[j + 2], i3 = g_col[j + 3];
        float2 a = __half22float2(H[(size_t)i0 * L + lane]);
        float2 b = __half22float2(H[(size_t)i1 * L + lane]);
        float2 c = __half22float2(H[(size_t)i2 * L + lane]);
        float2 d = __half22float2(H[(size_t)i3 * L + lane]);
        if (SRCSCALE) {
            float d0 = g_dis[i0], d1 = g_dis[i1], d2 = g_dis[i2], d3 = g_dis[i3];
            ax = fmaf(a.x, d0, ax); ay = fmaf(a.y, d0, ay);
            ax = fmaf(b.x, d1, ax); ay = fmaf(b.y, d1, ay);
            ax = fmaf(c.x, d2, ax); ay = fmaf(c.y, d2, ay);
            ax = fmaf(d.x, d3, ax); ay = fmaf(d.y, d3, ay);
        } else {
            ax += (a.x + b.x) + (c.x + d.x);
            ay += (a.y + b.y) + (c.y + d.y);
        }
    }
    for (; j < e; j++) {
        int i0 = g_col[j];
        float2 a = __half22float2(H[(size_t)i0 * L + lane]);
        if (SRCSCALE) {
            float d0 = g_dis[i0];
            ax = fmaf(a.x, d0, ax); ay = fmaf(a.y, d0, ay);
        } else {
            ax += a.x; ay += a.y;
        }
    }

    float2 bv = ((const float2*)bias)[lane];
    float ox = fmaxf(fmaf(ax, dn, bv.x), 0.f);
    float oy = fmaxf(fmaf(ay, dn, bv.y), 0.f);
    float2 r; r.x = ox; r.y = oy;
    ((float2*)out)[(size_t)warp * L + lane] = r;
}

// ---------------- final aggregation + bias + log_softmax (F=40, fp32) ----------------
__global__ void __launch_bounds__(256) k_agg_final(const float* __restrict__ H,
                                                   const float* __restrict__ bias,
                                                   float* __restrict__ out) {
    constexpr int L = FOUT / 2;  // 20
    int warp = (blockIdx.x * blockDim.x + threadIdx.x) >> 5;
    int lane = threadIdx.x & 31;
    if (warp >= NN) return;

    const float2* H2 = (const float2*)H;
    int s = g_rowptr[warp];
    int e = g_rowptr[warp + 1];

    float ax = 0.f, ay = 0.f;
    if (lane < L) {
        float2 self = H2[(size_t)warp * L + lane];
        ax = self.x; ay = self.y;
    }
    int j = s;
    for (; j + 4 <= e; j += 4) {
        int i0 = g_col[j], i1 = g_col[j + 1], i2 = g_col[j + 2], i3 = g_col[j + 3];
        if (lane < L) {
            float2 a = H2[(size_t)i0 * L + lane];
            float2 b = H2[(size_t)i1 * L + lane];
            float2 c = H2[(size_t)i2 * L + lane];
            float2 d = H2[(size_t)i3 * L + lane];
            ax += (a.x + b.x) + (c.x + d.x);
            ay += (a.y + b.y) + (c.y + d.y);
        }
    }
    for (; j < e; j++) {
        int i0 = g_col[j];
        if (lane < L) {
            float2 a = H2[(size_t)i0 * L + lane];
            ax += a.x; ay += a.y;
        }
    }

    float vx = -INFINITY, vy = -INFINITY;
    if (lane < L) {
        float dn = g_dis[warp];
        float2 bv = ((const float2*)bias)[lane];
        vx = fmaf(ax, dn, bv.x);
        vy = fmaf(ay, dn, bv.y);
    }

    float m = fmaxf(vx, vy);
#pragma unroll
    for (int off = 16; off > 0; off >>= 1)
        m = fmaxf(m, __shfl_xor_sync(0xFFFFFFFFu, m, off));

    float se = 0.f;
    if (lane < L) se = expf(vx - m) + expf(vy - m);
#pragma unroll
    for (int off = 16; off > 0; off >>= 1)
        se += __shfl_xor_sync(0xFFFFFFFFu, se, off);

    float ls = logf(se);
    if (lane < L) {
        float2 r; r.x = vx - m - ls; r.y = vy - m - ls;
        ((float2*)out)[(size_t)warp * L + lane] = r;
    }
}

// ---------------- launch ----------------
extern "C" void kernel_launch(void* const* d_in, const int* in_sizes, int n_in,
                              void* d_out, int out_size) {
    const float* x  = (const float*)d_in[0];
    const void*  ei = d_in[1];
    const float* W1 = (const float*)d_in[2];
    const float* b1 = (const float*)d_in[3];
    const float* W2 = (const float*)d_in[4];
    const float* b2 = (const float*)d_in[5];
    const float* W3 = (const float*)d_in[6];
    const float* b3 = (const float*)d_in[7];

    void *pH = nullptr, *pHh = nullptr, *pZ = nullptr, *pZero = nullptr;
    cudaGetSymbolAddress(&pH, g_H);
    cudaGetSymbolAddress(&pHh, g_Hh);
    cudaGetSymbolAddress(&pZ, g_Z);
    cudaGetSymbolAddress(&pZero, g_zero);
    float*   H  = (float*)pH;
    __half2* Hh = (__half2*)pHh;
    float*   Z  = (float*)pZ;

    const int TB = 256;
    int gE = (NE + TB - 1) / TB;
    int gGemm = (NN + 63) / 64;
    int gAgg  = (NN * 32 + TB - 1) / TB;

    // Fork: GEMM1 (no CSR dependency; dis-scaling deferred to agg1) overlapped
    // with the CSR build.
    cudaEventRecord(g_ss.evFork, 0);
    cudaStreamWaitEvent(g_ss.s1, g_ss.evFork, 0);
    k_gemm<FIN, FHID, false, true><<<gGemm, 128, 0, g_ss.s1>>>(x, W1, pHh);
    cudaEventRecord(g_ss.evJoin, g_ss.s1);

    // Main stream: CSR build (hist produces per-edge ranks; fill is atomic-free)
    cudaMemsetAsync(pZero, 0, (NN + 128) * sizeof(int));
    k_hist<<<gE, TB>>>(ei);
    k_scan_fused<<<NBLK, SCAN_B>>>();
    k_fill<<<gE, TB>>>(ei);

    // Join, then layer 1 aggregation (applies src-side dis)
    cudaStreamWaitEvent(0, g_ss.evJoin, 0);
    k_agg_h<true><<<gAgg, TB>>>(Hh, b1, Z);

    // Layer 2 (dis folded into GEMM epilogue)
    k_gemm<FHID, FHID, true, true><<<gGemm, 128>>>(Z, W2, pHh);
    k_agg_h<false><<<gAgg, TB>>>(Hh, b2, Z);

    // Layer 3 + log_softmax (fp32 messages)
    k_gemm<FHID, FOUT, true, false><<<gGemm, 128>>>(Z, W3, pH);
    k_agg_final<<<gAgg, TB>>>(H, b3, (float*)d_out);
}

// round 11
// speedup vs baseline: 1.0832x; 1.0832x over previous
#include <cuda_runtime.h>
#include <cuda_fp16.h>
#include <math.h>

#define NN 100000
#define NE 1200000
#define FIN 128
#define FHID 64
#define FOUT 40

typedef unsigned long long ull;

// ---------------- scratch (device globals) ----------------
// g_zero: [0,NN) = degree histogram, [NN, NN+128) = scan ready-flags. One memset.
__device__ int    g_zero[NN + 128];
__device__ int    g_rowptr[NN + 1];
__device__ int    g_cursor[NN];
__device__ int    g_col[NE];
__device__ float  g_dis[NN];
__device__ __half g_Hh[(size_t)NN * FHID];  // fp16 message buffer (layers 1-3)
__device__ float  g_Z[(size_t)NN * FHID];   // aggregated fp32 buffer

constexpr int SCAN_B = 1024;
constexpr int NBLK   = (NN + SCAN_B - 1) / SCAN_B;  // 98

// ---------------- side stream for capture fork-join (created pre-main) ----------------
struct SideStream {
    cudaStream_t s1;
    cudaEvent_t evFork, evJoin;
    SideStream() {
        cudaStreamCreateWithFlags(&s1, cudaStreamNonBlocking);
        cudaEventCreateWithFlags(&evFork, cudaEventDisableTiming);
        cudaEventCreateWithFlags(&evJoin, cudaEventDisableTiming);
    }
};
static SideStream g_ss;

// ---------------- packed f32x2 helpers (Blackwell FFMA2) ----------------
__device__ __forceinline__ ull bcast2(float f) {
    ull r;
    asm("mov.b64 %0, {%1, %1};" : "=l"(r) : "f"(f));
    return r;
}
__device__ __forceinline__ void fma2(ull& d, ull a, ull b) {
    asm("fma.rn.f32x2 %0, %1, %2, %0;" : "+l"(d) : "l"(a), "l"(b));
}
__device__ __forceinline__ void unpack2(float& lo, float& hi, ull v) {
    asm("mov.b64 {%0, %1}, %2;" : "=f"(lo), "=f"(hi) : "l"(v));
}

// ---------------- per-block edge dtype detection ----------------
__device__ __forceinline__ int detect_is64(const int* e) {
    int t = threadIdx.x;
    int pred = 1;
    if (t < 128) pred = (e[2 * t + 1] == 0);
    return __syncthreads_and(pred);
}

__device__ __forceinline__ int edge_at(const void* e, long long idx, int is64) {
    if (is64) return (int)((const long long*)e)[idx];
    return ((const int*)e)[idx];
}

// ---------------- degree histogram (RED path: atomic result unused) ----------------
__global__ void k_hist(const void* __restrict__ e) {
    int is64 = detect_is64((const int*)e);
    int i = blockIdx.x * blockDim.x + threadIdx.x;
    if (i < NE) {
        int d = edge_at(e, (long long)NE + i, is64);
        atomicAdd(&g_zero[d], 1);
    }
}

// ---------------- single-pass scan: deg -> rowptr, cursor, dis ----------------
__global__ void __launch_bounds__(SCAN_B) k_scan_fused() {
    __shared__ int wsum[32];
    __shared__ int s_off;
    int b    = blockIdx.x;
    int tid  = threadIdx.x;
    int lane = tid & 31;
    int wid  = tid >> 5;
    int idx  = b * SCAN_B + tid;
    int* ready = &g_zero[NN];

    int v = (idx < NN) ? g_zero[idx] : 0;
    if (idx < NN) g_dis[idx] = rsqrtf((float)(v + 1));
    if (tid == 0) s_off = 0;

    int x = v;
#pragma unroll
    for (int off = 1; off < 32; off <<= 1) {
        int y = __shfl_up_sync(0xFFFFFFFFu, x, off);
        if (lane >= off) x += y;
    }
    if (lane == 31) wsum[wid] = x;
    __syncthreads();
    if (wid == 0) {
        int w = wsum[lane];
#pragma unroll
        for (int off = 1; off < 32; off <<= 1) {
            int y = __shfl_up_sync(0xFFFFFFFFu, w, off);
            if (lane >= off) w += y;
        }
        wsum[lane] = w;
    }
    __syncthreads();
    int inc = x + ((wid > 0) ? wsum[wid - 1] : 0);

    if (tid == SCAN_B - 1)
        atomicExch(&ready[b], inc + 1);

    if (tid < b) {
        int a;
        do { a = atomicAdd(&ready[tid], 0); } while (a == 0);
        atomicAdd(&s_off, a - 1);
    }
    __syncthreads();
    int off = s_off;

    if (idx < NN) {
        int ip = off + inc;
        g_rowptr[idx + 1] = ip;
        g_cursor[idx]     = ip - v;  // exclusive prefix
    }
    if (idx == 0) g_rowptr[0] = 0;
}

// ---------------- CSR fill (ATOM cursor — round-5 placement) ----------------
__global__ void k_fill(const void* __restrict__ e) {
    int is64 = detect_is64((const int*)e);
    int i = blockIdx.x * blockDim.x + threadIdx.x;
    if (i < NE) {
        int d = edge_at(e, (long long)NE + i, is64);
        int s = edge_at(e, i, is64);
        int pos = atomicAdd(&g_cursor[d], 1);
        g_col[pos] = s;
    }
}

// ---------------- GEMM (64x64 tile, known good) ----------------
// out[i,c] = (SCALE ? dis[i] : 1) * sum_k X[i,k]*W[k,c]
// OUTH: fp16 output, row stride NOUT halfs (NOUT multiple of 4).
template <int K, int NOUT, bool SCALE, bool OUTH>
__global__ void __launch_bounds__(128) k_gemm(const float* __restrict__ X,
                                              const float* __restrict__ W,
                                              void* __restrict__ outv) {
    constexpr int BM = 64;
    constexpr int BN = 64;
    constexpr int KC = 32;
    __shared__ float Ws[K][BN];
    __shared__ float Xs[KC][BM + 4];

    int t  = threadIdx.x;
    int m0 = blockIdx.x * BM;
    int rbase = (t >> 4) * 8;
    int cbase = (t & 15) * 4;

    for (int i = t; i < K * BN; i += 128) {
        int k = i / BN, c = i % BN;
        Ws[k][c] = (c < NOUT) ? W[k * NOUT + c] : 0.0f;
    }

    ull acc[4][4];
#pragma unroll
    for (int rp = 0; rp < 4; rp++)
#pragma unroll
        for (int c = 0; c < 4; c++) acc[rp][c] = 0ull;

    __syncthreads();

    for (int kc = 0; kc < K; kc += KC) {
#pragma unroll
        for (int i = 0; i < 4; i++) {
            int v = t + i * 128;
            int r = v >> 3;
            int q = v & 7;
            int row = m0 + r;
            float4 f = make_float4(0.f, 0.f, 0.f, 0.f);
            if (row < NN)
                f = *(const float4*)&X[(size_t)row * K + kc + q * 4];
            Xs[q * 4 + 0][r] = f.x;
            Xs[q * 4 + 1][r] = f.y;
            Xs[q * 4 + 2][r] = f.z;
            Xs[q * 4 + 3][r] = f.w;
        }
        __syncthreads();

#pragma unroll
        for (int kk = 0; kk < KC; kk++) {
            float4 wv = *(const float4*)&Ws[kc + kk][cbase];
            ull wb0 = bcast2(wv.x);
            ull wb1 = bcast2(wv.y);
            ull wb2 = bcast2(wv.z);
            ull wb3 = bcast2(wv.w);
            ulonglong2 xp0 = *(const ulonglong2*)&Xs[kk][rbase];
            ulonglong2 xp1 = *(const ulonglong2*)&Xs[kk][rbase + 4];
            ull xr[4] = {xp0.x, xp0.y, xp1.x, xp1.y};
#pragma unroll
            for (int rp = 0; rp < 4; rp++) {
                fma2(acc[rp][0], xr[rp], wb0);
                fma2(acc[rp][1], xr[rp], wb1);
                fma2(acc[rp][2], xr[rp], wb2);
                fma2(acc[rp][3], xr[rp], wb3);
            }
        }
        __syncthreads();
    }

#pragma unroll
    for (int rp = 0; rp < 4; rp++) {
        int row0 = m0 + rbase + 2 * rp;
        int row1 = row0 + 1;
        float ds0 = 1.f, ds1 = 1.f;
        if (SCALE) {
            ds0 = (row0 < NN) ? g_dis[row0] : 0.f;
            ds1 = (row1 < NN) ? g_dis[row1] : 0.f;
        }
        float v0[4], v1[4];
#pragma unroll
        for (int c = 0; c < 4; c++) unpack2(v0[c], v1[c], acc[rp][c]);

        if (OUTH) {
            __half* out = (__half*)outv;
            if (cbase < NOUT) {  // cbase multiple of 4; NOUT multiple of 4
                if (row0 < NN) {
                    __half2 h0 = __floats2half2_rn(v0[0] * ds0, v0[1] * ds0);
                    __half2 h1 = __floats2half2_rn(v0[2] * ds0, v0[3] * ds0);
                    uint2 u; u.x = *(unsigned*)&h0; u.y = *(unsigned*)&h1;
                    *(uint2*)&out[(size_t)row0 * NOUT + cbase] = u;
                }
                if (row1 < NN) {
                    __half2 h0 = __floats2half2_rn(v1[0] * ds1, v1[1] * ds1);
                    __half2 h1 = __floats2half2_rn(v1[2] * ds1, v1[3] * ds1);
                    uint2 u; u.x = *(unsigned*)&h0; u.y = *(unsigned*)&h1;
                    *(uint2*)&out[(size_t)row1 * NOUT + cbase] = u;
                }
            }
        } else {
            float* out = (float*)outv;
#pragma unroll
            for (int c = 0; c < 4; c++) {
                int cc = cbase + c;
                if (cc < NOUT) {
                    if (row0 < NN) out[(size_t)row0 * NOUT + cc] = v0[c] * ds0;
                    if (row1 < NN) out[(size_t)row1 * NOUT + cc] = v1[c] * ds1;
                }
            }
        }
    }
}

// ---------------- fp16 aggregation (F=64): warp per node, fp32 accumulate ----------------
// SRCSCALE=false: H pre-scaled by dis; out = relu(dis[d]*(Σ H[s] + H[d]) + b)
// SRCSCALE=true : H unscaled;         out = relu(dis[d]*(Σ dis[s]H[s] + dis[d]H[d]) + b)
template <bool SRCSCALE>
__global__ void __launch_bounds__(256) k_agg_h(const __half2* __restrict__ H,
                                               const float* __restrict__ bias,
                                               float* __restrict__ out) {
    constexpr int L = FHID / 2;  // 32 half2 per row = full warp
    int warp = (blockIdx.x * blockDim.x + threadIdx.x) >> 5;
    int lane = threadIdx.x & 31;
    if (warp >= NN) return;

    int s = g_rowptr[warp];
    int e = g_rowptr[warp + 1];
    float dn = g_dis[warp];

    float2 self = __half22float2(H[(size_t)warp * L + lane]);
    float sc = SRCSCALE ? dn : 1.f;
    float ax = self.x * sc, ay = self.y * sc;

    int j = s;
    for (; j + 4 <= e; j += 4) {
        int i0 = g_col[j], i1 = g_col[j + 1], i2 = g_col[j + 2], i3 = g_col[j + 3];
        float2 a = __half22float2(H[(size_t)i0 * L + lane]);
        float2 b = __half22float2(H[(size_t)i1 * L + lane]);
        float2 c = __half22float2(H[(size_t)i2 * L + lane]);
        float2 d = __half22float2(H[(size_t)i3 * L + lane]);
        if (SRCSCALE) {
            float d0 = g_dis[i0], d1 = g_dis[i1], d2 = g_dis[i2], d3 = g_dis[i3];
            ax = fmaf(a.x, d0, ax); ay = fmaf(a.y, d0, ay);
            ax = fmaf(b.x, d1, ax); ay = fmaf(b.y, d1, ay);
            ax = fmaf(c.x, d2, ax); ay = fmaf(c.y, d2, ay);
            ax = fmaf(d.x, d3, ax); ay = fmaf(d.y, d3, ay);
        } else {
            ax += (a.x + b.x) + (c.x + d.x);
            ay += (a.y + b.y) + (c.y + d.y);
        }
    }
    for (; j < e; j++) {
        int i0 = g_col[j];
        float2 a = __half22float2(H[(size_t)i0 * L + lane]);
        if (SRCSCALE) {
            float d0 = g_dis[i0];
            ax = fmaf(a.x, d0, ax); ay = fmaf(a.y, d0, ay);
        } else {
            ax += a.x; ay += a.y;
        }
    }

    float2 bv = ((const float2*)bias)[lane];
    float ox = fmaxf(fmaf(ax, dn, bv.x), 0.f);
    float oy = fmaxf(fmaf(ay, dn, bv.y), 0.f);
    float2 r; r.x = ox; r.y = oy;
    ((float2*)out)[(size_t)warp * L + lane] = r;
}

// ---------------- final aggregation + bias + log_softmax (F=40, fp16 messages) ----------------
__global__ void __launch_bounds__(256) k_agg_final(const __half2* __restrict__ H,
                                                   const float* __restrict__ bias,
                                                   float* __restrict__ out) {
    constexpr int L = FOUT / 2;  // 20 half2 lanes
    int warp = (blockIdx.x * blockDim.x + threadIdx.x) >> 5;
    int lane = threadIdx.x & 31;
    if (warp >= NN) return;

    int s = g_rowptr[warp];
    int e = g_rowptr[warp + 1];

    float ax = 0.f, ay = 0.f;
    if (lane < L) {
        float2 self = __half22float2(H[(size_t)warp * L + lane]);
        ax = self.x; ay = self.y;
    }
    int j = s;
    for (; j + 4 <= e; j += 4) {
        int i0 = g_col[j], i1 = g_col[j + 1], i2 = g_col[j + 2], i3 = g_col[j + 3];
        if (lane < L) {
            float2 a = __half22float2(H[(size_t)i0 * L + lane]);
            float2 b = __half22float2(H[(size_t)i1 * L + lane]);
            float2 c = __half22float2(H[(size_t)i2 * L + lane]);
            float2 d = __half22float2(H[(size_t)i3 * L + lane]);
            ax += (a.x + b.x) + (c.x + d.x);
            ay += (a.y + b.y) + (c.y + d.y);
        }
    }
    for (; j < e; j++) {
        int i0 = g_col[j];
        if (lane < L) {
            float2 a = __half22float2(H[(size_t)i0 * L + lane]);
            ax += a.x; ay += a.y;
        }
    }

    float vx = -INFINITY, vy = -INFINITY;
    if (lane < L) {
        float dn = g_dis[warp];
        float2 bv = ((const float2*)bias)[lane];
        vx = fmaf(ax, dn, bv.x);
        vy = fmaf(ay, dn, bv.y);
    }

    float m = fmaxf(vx, vy);
#pragma unroll
    for (int off = 16; off > 0; off >>= 1)
        m = fmaxf(m, __shfl_xor_sync(0xFFFFFFFFu, m, off));

    float se = 0.f;
    if (lane < L) se = expf(vx - m) + expf(vy - m);
#pragma unroll
    for (int off = 16; off > 0; off >>= 1)
        se += __shfl_xor_sync(0xFFFFFFFFu, se, off);

    float ls = logf(se);
    if (lane < L) {
        float2 r; r.x = vx - m - ls; r.y = vy - m - ls;
        ((float2*)out)[(size_t)warp * L + lane] = r;
    }
}

// ---------------- launch ----------------
extern "C" void kernel_launch(void* const* d_in, const int* in_sizes, int n_in,
                              void* d_out, int out_size) {
    const float* x  = (const float*)d_in[0];
    const void*  ei = d_in[1];
    const float* W1 = (const float*)d_in[2];
    const float* b1 = (const float*)d_in[3];
    const float* W2 = (const float*)d_in[4];
    const float* b2 = (const float*)d_in[5];
    const float* W3 = (const float*)d_in[6];
    const float* b3 = (const float*)d_in[7];

    void *pHh = nullptr, *pZ = nullptr, *pZero = nullptr;
    cudaGetSymbolAddress(&pHh, g_Hh);
    cudaGetSymbolAddress(&pZ, g_Z);
    cudaGetSymbolAddress(&pZero, g_zero);
    __half2* Hh = (__half2*)pHh;
    float*   Z  = (float*)pZ;

    const int TB = 256;
    int gE = (NE + TB - 1) / TB;
    int gGemm = (NN + 63) / 64;
    int gAgg  = (NN * 32 + TB - 1) / TB;

    // Fork: GEMM1 (no CSR dependency; dis-scaling deferred to agg1) overlapped
    // with the CSR build.
    cudaEventRecord(g_ss.evFork, 0);
    cudaStreamWaitEvent(g_ss.s1, g_ss.evFork, 0);
    k_gemm<FIN, FHID, false, true><<<gGemm, 128, 0, g_ss.s1>>>(x, W1, pHh);
    cudaEventRecord(g_ss.evJoin, g_ss.s1);

    // Main stream: CSR build (hist = RED path, fill = ATOM cursor)
    cudaMemsetAsync(pZero, 0, (NN + 128) * sizeof(int));
    k_hist<<<gE, TB>>>(ei);
    k_scan_fused<<<NBLK, SCAN_B>>>();
    k_fill<<<gE, TB>>>(ei);

    // Join, then layer 1 aggregation (applies src-side dis)
    cudaStreamWaitEvent(0, g_ss.evJoin, 0);
    k_agg_h<true><<<gAgg, TB>>>(Hh, b1, Z);

    // Layer 2 (dis folded into GEMM epilogue)
    k_gemm<FHID, FHID, true, true><<<gGemm, 128>>>(Z, W2, pHh);
    k_agg_h<false><<<gAgg, TB>>>(Hh, b2, Z);

    // Layer 3: fp16 messages now (half the gather bytes in agg_final)
    k_gemm<FHID, FOUT, true, true><<<gGemm, 128>>>(Z, W3, pHh);
    k_agg_final<<<gAgg, TB>>>(Hh, b3, (float*)d_out);
}